// round 7
// baseline (speedup 1.0000x reference)
#include <cuda_runtime.h>
#include <cuda_fp16.h>
#include <cstdint>

#define THREADS     256
#define B_ROWS      256
#define D_K         2048
#define N_FEAT      65536
#define N_TILE      64
#define KC          64
#define NSTAGE      (D_K / KC)         // 32
#define STG_BYTES   16384              // fp32 B staging (single, self-read)
#define BB_BYTES    8192               // fp16 B buffer (double)
#define SMEM_DYN    (1024 + STG_BYTES + 2 * BB_BYTES)

// 1MB fragment-major fp16 A: u = ((s*16 + mtile)*4 + ks)*32 + lane, 16B per u
__device__ uint4 g_afrag[NSTAGE * 16 * 4 * 32];

static __device__ __forceinline__ uint32_t smem_u32(const void* p) {
    uint32_t a;
    asm("{ .reg .u64 t; cvta.to.shared.u64 t, %1; cvt.u32.u64 %0, t; }"
        : "=r"(a) : "l"(p));
    return a;
}

#define CP_ASYNC16(dst, src) \
    asm volatile("cp.async.cg.shared.global [%0], [%1], 16;" \
                 :: "r"(dst), "l"(src) : "memory")
#define CP_COMMIT() asm volatile("cp.async.commit_group;" ::: "memory")
#define CP_WAIT0()  asm volatile("cp.async.wait_group 0;"  ::: "memory")

#define LDSM_X4(r, addr) \
    asm volatile("ldmatrix.sync.aligned.m8n8.x4.shared.b16 {%0,%1,%2,%3}, [%4];" \
        : "=r"((r)[0]), "=r"((r)[1]), "=r"((r)[2]), "=r"((r)[3]) : "r"(addr))

#define MMA16816(c, a, b0, b1) \
    asm volatile("mma.sync.aligned.m16n8k16.row.col.f32.f16.f16.f32 " \
        "{%0,%1,%2,%3}, {%4,%5,%6,%7}, {%8,%9}, {%0,%1,%2,%3};" \
        : "+f"((c)[0]), "+f"((c)[1]), "+f"((c)[2]), "+f"((c)[3]) \
        : "r"((a)[0]), "r"((a)[1]), "r"((a)[2]), "r"((a)[3]), "r"(b0), "r"(b1))

#define STS64(addr, v0, v1) \
    asm volatile("st.shared.v2.b32 [%0], {%1,%2};" \
                 :: "r"(addr), "r"(v0), "r"(v1) : "memory")

#define LDS128F(f, addr) \
    asm volatile("ld.shared.v4.f32 {%0,%1,%2,%3}, [%4];" \
        : "=f"((f)[0]), "=f"((f)[1]), "=f"((f)[2]), "=f"((f)[3]) : "r"(addr))

// ---------------- pre-kernel: inputs fp32 -> fragment-major fp16 A ----------------
// Fragment regs for mma.m16n8k16 A (row-major), lane l:
//   r0=(row,k) r1=(row+8,k) r2=(row,k+8) r3=(row+8,k+8), row=l>>2, k=(l&3)*2 (+1)
__global__ void build_afrag(const float* __restrict__ in) {
    const int u  = blockIdx.x * blockDim.x + threadIdx.x;   // 65536
    const int l  = u & 31;
    const int ks = (u >> 5) & 3;
    const int mt = (u >> 7) & 15;
    const int s  = u >> 11;
    const int row = mt * 16 + (l >> 2);
    const int col = s * KC + ks * 16 + (l & 3) * 2;
    const float* r0 = in + (size_t)row * D_K;
    const float* r1 = in + (size_t)(row + 8) * D_K;
    __half2 h0 = __floats2half2_rn(r0[col],     r0[col + 1]);
    __half2 h1 = __floats2half2_rn(r1[col],     r1[col + 1]);
    __half2 h2 = __floats2half2_rn(r0[col + 8], r0[col + 9]);
    __half2 h3 = __floats2half2_rn(r1[col + 8], r1[col + 9]);
    uint4 v;
    v.x = *reinterpret_cast<uint32_t*>(&h0);
    v.y = *reinterpret_cast<uint32_t*>(&h1);
    v.z = *reinterpret_cast<uint32_t*>(&h2);
    v.w = *reinterpret_cast<uint32_t*>(&h3);
    g_afrag[u] = v;
}

// ---------------- main GEMM kernel ----------------
__global__ __launch_bounds__(THREADS, 2)
void gemm_hmma_kernel(const float* __restrict__ feats, float* __restrict__ out) {
    extern __shared__ char dsm[];
    const uint32_t raw = smem_u32(dsm);
    const uint32_t SB  = (raw + 1023u) & ~1023u;
    const uint32_t STG = SB;                 // 16KB fp32 B staging
    const uint32_t BB0 = SB + STG_BYTES;     // fp16 B buffers (8KB x2)

    const int tid = threadIdx.x;
    const int wid = tid >> 5;
    const int lid = tid & 31;
    const int wm  = wid & 3;    // 4 M-warps x 64 rows
    const int wn  = wid >> 2;   // 2 N-warps x 32 cols
    const int n0  = blockIdx.x * N_TILE;

    // ---- B staging coordinates (row = tid>>2, 4 float4 chunks per thread) ----
    const int brow = tid >> 2;
    const int bj   = tid & 3;
    const float* bSrc = feats + (size_t)(n0 + brow) * D_K + bj * 4;
    uint32_t bsts_off[4];
    #pragma unroll
    for (int i = 0; i < 4; ++i) {
        uint32_t ob = ((uint32_t)brow << 7) | ((uint32_t)(bj + 4 * i) << 3);
        bsts_off[i] = ob ^ ((ob >> 3) & 0x70);
    }
    const uint32_t stg_slot = STG + (uint32_t)tid * 16;   // +i*4096 per chunk

    // ---- A fragment pointer (per warp/lane) ----
    const char* paw = (const char*)g_afrag + (size_t)(wm * 4) * 2048 + (size_t)lid * 16;

    // ---- B ldmatrix addressing (R6-validated) ----
    const uint32_t b_row  = (uint32_t)(wn * 32 + ((lid >> 4) << 3) + (lid & 7));
    const uint32_t b_lane = b_row << 7;
    const uint32_t b_sw   = b_row & 7;
    const uint32_t b_kc   = (uint32_t)((lid >> 3) & 1);

    float acc[4][4][4];
    #pragma unroll
    for (int mf = 0; mf < 4; ++mf)
        #pragma unroll
        for (int nf = 0; nf < 4; ++nf)
            #pragma unroll
            for (int k = 0; k < 4; ++k)
                acc[mf][nf][k] = 0.0f;

    // ---- prologue: cp.async B(0) staging + A(0,ks0) fragment loads ----
    #pragma unroll
    for (int i = 0; i < 4; ++i)
        CP_ASYNC16(stg_slot + i * 4096, bSrc + i * 16);
    CP_COMMIT();

    uint32_t ar0[4][4], ar1[4][4];
    #pragma unroll
    for (int mf = 0; mf < 4; ++mf)
        *reinterpret_cast<uint4*>(ar0[mf]) =
            *reinterpret_cast<const uint4*>(paw + mf * 2048);

    for (int s = 0; s < NSTAGE; ++s) {
        const uint32_t Bb = BB0 + (uint32_t)(s & 1) * BB_BYTES;

        // consume staged fp32 B(s) (own slots), convert, STS fp16
        CP_WAIT0();
        #pragma unroll
        for (int i = 0; i < 4; ++i) {
            float f[4];
            LDS128F(f, stg_slot + i * 4096);
            __half2 h0 = __floats2half2_rn(f[0], f[1]);
            __half2 h1 = __floats2half2_rn(f[2], f[3]);
            STS64(Bb + bsts_off[i],
                  *reinterpret_cast<uint32_t*>(&h0),
                  *reinterpret_cast<uint32_t*>(&h1));
        }
        __syncthreads();

        // issue B(s+1) staging (after barrier: all threads consumed staging(s))
        if (s + 1 < NSTAGE) {
            const float* bs = bSrc + (s + 1) * KC;
            #pragma unroll
            for (int i = 0; i < 4; ++i)
                CP_ASYNC16(stg_slot + i * 4096, bs + i * 16);
            CP_COMMIT();
        }

        // ---- compute: 4 k-steps, A frags prefetched one step ahead ----
        const size_t soff  = (size_t)s * 32768;
        const size_t snoff = (size_t)((s + 1 < NSTAGE) ? s + 1 : s) * 32768;
        #pragma unroll
        for (int ks = 0; ks < 4; ++ks) {
            uint32_t (*cur)[4] = (ks & 1) ? ar1 : ar0;
            uint32_t (*nxt)[4] = (ks & 1) ? ar0 : ar1;
            const size_t nko = (ks < 3) ? (soff + (size_t)(ks + 1) * 512) : snoff;
            #pragma unroll
            for (int mf = 0; mf < 4; ++mf)
                *reinterpret_cast<uint4*>(nxt[mf]) =
                    *reinterpret_cast<const uint4*>(paw + nko + mf * 2048);

            uint32_t br[4], br2[4];
            const uint32_t b_ch = ((b_kc + 2u * ks) ^ b_sw) << 4;
            LDSM_X4(br,  Bb + b_lane + b_ch);                 // cols 0-15 of warp span
            LDSM_X4(br2, Bb + ((b_row + 16u) << 7) + b_ch);   // cols 16-31 (same &7)

            #pragma unroll
            for (int mf = 0; mf < 4; ++mf) {
                MMA16816(acc[mf][0], cur[mf], br[0],  br[1]);
                MMA16816(acc[mf][1], cur[mf], br[2],  br[3]);
                MMA16816(acc[mf][2], cur[mf], br2[0], br2[1]);
                MMA16816(acc[mf][3], cur[mf], br2[2], br2[3]);
            }
        }
        __syncthreads();
    }

    // ---- epilogue: direct STG.64, 32B-sector aligned ----
    const int mrow = wm * 64 + (lid >> 2);
    const int ncol = n0 + wn * 32 + 2 * (lid & 3);
    #pragma unroll
    for (int mf = 0; mf < 4; ++mf) {
        float* r0 = out + (size_t)(mrow + mf * 16) * N_FEAT;
        float* r1 = r0 + (size_t)8 * N_FEAT;
        #pragma unroll
        for (int nf = 0; nf < 4; ++nf) {
            const int c = ncol + nf * 8;
            *reinterpret_cast<float2*>(r0 + c) =
                make_float2(acc[mf][nf][0], acc[mf][nf][1]);
            *reinterpret_cast<float2*>(r1 + c) =
                make_float2(acc[mf][nf][2], acc[mf][nf][3]);
        }
    }
}

// ---------------- launch ----------------
extern "C" void kernel_launch(void* const* d_in, const int* in_sizes, int n_in,
                              void* d_out, int out_size) {
    const float* inputs = (const float*)d_in[0];   // [256, 2048] fp32
    const float* feats  = (const float*)d_in[3];   // [65536, 2048] fp32
    float* out = (float*)d_out;                    // [256, 65536] fp32

    cudaFuncSetAttribute(gemm_hmma_kernel,
                         cudaFuncAttributeMaxDynamicSharedMemorySize, SMEM_DYN);

    build_afrag<<<256, 256>>>(inputs);
    gemm_hmma_kernel<<<N_FEAT / N_TILE, THREADS, SMEM_DYN>>>(feats, out);
}

// round 8
// speedup vs baseline: 1.2808x; 1.2808x over previous
#include <cuda_runtime.h>
#include <cuda_fp16.h>
#include <cstdint>

#define THREADS     256
#define B_ROWS      256
#define D_K         2048
#define N_FEAT      65536
#define N_TILE      64
#define KC          64
#define NSTAGE      (D_K / KC)            // 32
#define A_ST        (B_ROWS * KC * 2)     // 32768 fp16 A per stage
#define B_ST        (N_TILE * KC * 2)     // 8192  fp16 B per stage
#define SMEM_DYN    (128 + 3 * A_ST + 2 * B_ST)   // 114816

// 1MB fp16 copy of `inputs` (pre-converted once per launch, L2-resident)
__device__ __half g_a16[B_ROWS * D_K];

static __device__ __forceinline__ uint32_t smem_u32(const void* p) {
    uint32_t a;
    asm("{ .reg .u64 t; cvta.to.shared.u64 t, %1; cvt.u32.u64 %0, t; }"
        : "=r"(a) : "l"(p));
    return a;
}

#define CP_ASYNC16(dst, src) \
    asm volatile("cp.async.cg.shared.global [%0], [%1], 16;" \
                 :: "r"(dst), "l"(src) : "memory")
#define CP_COMMIT() asm volatile("cp.async.commit_group;" ::: "memory")
#define CP_WAIT1()  asm volatile("cp.async.wait_group 1;"  ::: "memory")

#define LDSM_X4(r, addr) \
    asm volatile("ldmatrix.sync.aligned.m8n8.x4.shared.b16 {%0,%1,%2,%3}, [%4];" \
        : "=r"((r)[0]), "=r"((r)[1]), "=r"((r)[2]), "=r"((r)[3]) : "r"(addr))

#define MMA16816(c, a, b0, b1) \
    asm volatile("mma.sync.aligned.m16n8k16.row.col.f32.f16.f16.f32 " \
        "{%0,%1,%2,%3}, {%4,%5,%6,%7}, {%8,%9}, {%0,%1,%2,%3};" \
        : "+f"((c)[0]), "+f"((c)[1]), "+f"((c)[2]), "+f"((c)[3]) \
        : "r"((a)[0]), "r"((a)[1]), "r"((a)[2]), "r"((a)[3]), "r"(b0), "r"(b1))

#define STS64(addr, v0, v1) \
    asm volatile("st.shared.v2.b32 [%0], {%1,%2};" \
                 :: "r"(addr), "r"(v0), "r"(v1) : "memory")

// ---------------- pre-kernel: inputs fp32 -> fp16 scratch ----------------
__global__ void cvt_a_kernel(const float* __restrict__ inputs) {
    int i = blockIdx.x * blockDim.x + threadIdx.x;
    if (i < (B_ROWS * D_K) / 2) {
        float2 v = reinterpret_cast<const float2*>(inputs)[i];
        reinterpret_cast<__half2*>(g_a16)[i] = __floats2half2_rn(v.x, v.y);
    }
}

// ---------------- main GEMM kernel ----------------
__global__ __launch_bounds__(THREADS, 2)
void gemm_hmma_kernel(const float* __restrict__ feats, float* __restrict__ out) {
    extern __shared__ char dsm[];
    const uint32_t raw = smem_u32(dsm);
    const uint32_t SB  = (raw + 127u) & ~127u;   // 128-aligned: bank pattern preserved
    const uint32_t BB0 = SB + 3 * A_ST;          // two fp16 B buffers after 3 A buffers

    const int tid = threadIdx.x;
    const int wid = tid >> 5;
    const int lid = tid & 31;
    const int wm  = wid & 3;    // 4 M-warps x 64 rows
    const int wn  = wid >> 2;   // 2 N-warps x 32 cols
    const int n0  = blockIdx.x * N_TILE;

    // ---- A cp.async staging: 256 rows x 128B/stage; 8x16B per thread ----
    const char* aSrc = (const char*)(g_a16 + (size_t)(tid >> 3) * D_K + (tid & 7) * 8);
    const uint32_t aOff = ((uint32_t)(tid >> 3) << 7) |
                          ((uint32_t)((tid & 7) ^ ((tid >> 3) & 7)) << 4);

    // ---- B LDG staging: 64 rows x 64 fp32/stage; 4x float4 per thread ----
    const int brow = tid >> 2;
    const int bj   = tid & 3;
    const float* bSrc = feats + (size_t)(n0 + brow) * D_K + bj * 4;
    uint32_t bsts_off[4];
    #pragma unroll
    for (int i = 0; i < 4; ++i) {
        uint32_t ob = ((uint32_t)brow << 7) | ((uint32_t)(bj + 4 * i) << 3);
        bsts_off[i] = ob ^ ((ob >> 3) & 0x70);
    }

    // ---- ldmatrix fragment addressing (swizzle-correct per k-step) ----
    const uint32_t a_lane = (uint32_t)(wm * 64 + (lid & 15)) << 7;
    const uint32_t a_sw   = (uint32_t)(lid & 7);
    const uint32_t a_kc   = (uint32_t)(lid >> 4);
    const uint32_t b_row  = (uint32_t)(wn * 32 + ((lid >> 4) << 3) + (lid & 7));
    const uint32_t b_lane = b_row << 7;
    const uint32_t b_sw   = b_row & 7;
    const uint32_t b_kc   = (uint32_t)((lid >> 3) & 1);

    float acc[4][4][4];
    #pragma unroll
    for (int mf = 0; mf < 4; ++mf)
        #pragma unroll
        for (int nf = 0; nf < 4; ++nf)
            #pragma unroll
            for (int k = 0; k < 4; ++k)
                acc[mf][nf][k] = 0.0f;

    float fst[16];   // staged raw fp32 B for current stage

    // ---- prologue: B(0) LDG; A(0), A(1) cp.async (distance-2 pipeline) ----
    #pragma unroll
    for (int i = 0; i < 4; ++i) {
        const float4 v = *reinterpret_cast<const float4*>(bSrc + i * 16);
        fst[i*4+0] = v.x; fst[i*4+1] = v.y; fst[i*4+2] = v.z; fst[i*4+3] = v.w;
    }
    #pragma unroll
    for (int i = 0; i < 8; ++i)
        CP_ASYNC16(SB + aOff + i * 4096, aSrc + (size_t)i * 32 * D_K * 2);
    CP_COMMIT();                                   // g0 = A(0)
    #pragma unroll
    for (int i = 0; i < 8; ++i)
        CP_ASYNC16(SB + A_ST + aOff + i * 4096,
                   aSrc + (size_t)KC * 2 + (size_t)i * 32 * D_K * 2);
    CP_COMMIT();                                   // g1 = A(1)

    for (int s = 0; s < NSTAGE; ++s) {
        const uint32_t Ab = SB + (uint32_t)(s % 3) * A_ST;
        const uint32_t Bb = BB0 + (uint32_t)(s & 1) * B_ST;

        // STS B(s): convert staged fp32 -> fp16
        #pragma unroll
        for (int i = 0; i < 4; ++i) {
            __half2 h0 = __floats2half2_rn(fst[i*4+0], fst[i*4+1]);
            __half2 h1 = __floats2half2_rn(fst[i*4+2], fst[i*4+3]);
            STS64(Bb + bsts_off[i],
                  *reinterpret_cast<uint32_t*>(&h0),
                  *reinterpret_cast<uint32_t*>(&h1));
        }
        CP_WAIT1();          // A(s) landed (A(s+1) may still be in flight)
        __syncthreads();     // single barrier per stage

        // issue A(s+2) (always commit to keep group accounting exact) + B(s+1) LDG
        if (s + 2 < NSTAGE) {
            const uint32_t An = SB + (uint32_t)((s + 2) % 3) * A_ST;
            const char* as = aSrc + (size_t)(s + 2) * (KC * 2);
            #pragma unroll
            for (int i = 0; i < 8; ++i)
                CP_ASYNC16(An + aOff + i * 4096, as + (size_t)i * 32 * D_K * 2);
        }
        CP_COMMIT();
        if (s + 1 < NSTAGE) {
            const int kc1 = (s + 1) * KC;   // in FLOAT elements
            #pragma unroll
            for (int i = 0; i < 4; ++i) {
                const float4 v = *reinterpret_cast<const float4*>(bSrc + kc1 + i * 16);
                fst[i*4+0] = v.x; fst[i*4+1] = v.y; fst[i*4+2] = v.z; fst[i*4+3] = v.w;
            }
        }

        // ---- compute stage s: 4 k-steps of 16 ----
        #pragma unroll
        for (int ks = 0; ks < 4; ++ks) {
            uint32_t ar[4][4], br[4], br2[4];
            const uint32_t a_ch = ((a_kc + 2u * ks) ^ a_sw) << 4;
            #pragma unroll
            for (int mf = 0; mf < 4; ++mf)
                LDSM_X4(ar[mf], Ab + a_lane + (uint32_t)(mf * 2048) + a_ch);
            const uint32_t b_ch = ((b_kc + 2u * ks) ^ b_sw) << 4;
            LDSM_X4(br,  Bb + b_lane + b_ch);               // warp cols 0-15 (nf 0,1)
            LDSM_X4(br2, Bb + ((b_row + 16u) << 7) + b_ch); // cols 16-31; (row+16)&7==row&7
            #pragma unroll
            for (int mf = 0; mf < 4; ++mf) {
                MMA16816(acc[mf][0], ar[mf], br[0],  br[1]);
                MMA16816(acc[mf][1], ar[mf], br[2],  br[3]);
                MMA16816(acc[mf][2], ar[mf], br2[0], br2[1]);
                MMA16816(acc[mf][3], ar[mf], br2[2], br2[3]);
            }
        }
        // no trailing barrier: next stage's single sync orders all reuse hazards
    }

    // ---- epilogue: direct STG.64, 32B-sector aligned ----
    const int mrow = wm * 64 + (lid >> 2);
    const int ncol = n0 + wn * 32 + 2 * (lid & 3);
    #pragma unroll
    for (int mf = 0; mf < 4; ++mf) {
        float* r0 = out + (size_t)(mrow + mf * 16) * N_FEAT;
        float* r1 = r0 + (size_t)8 * N_FEAT;
        #pragma unroll
        for (int nf = 0; nf < 4; ++nf) {
            const int c = ncol + nf * 8;
            *reinterpret_cast<float2*>(r0 + c) =
                make_float2(acc[mf][nf][0], acc[mf][nf][1]);
            *reinterpret_cast<float2*>(r1 + c) =
                make_float2(acc[mf][nf][2], acc[mf][nf][3]);
        }
    }
}

// ---------------- launch ----------------
extern "C" void kernel_launch(void* const* d_in, const int* in_sizes, int n_in,
                              void* d_out, int out_size) {
    const float* inputs = (const float*)d_in[0];   // [256, 2048] fp32
    const float* feats  = (const float*)d_in[3];   // [65536, 2048] fp32
    float* out = (float*)d_out;                    // [256, 65536] fp32

    cudaFuncSetAttribute(gemm_hmma_kernel,
                         cudaFuncAttributeMaxDynamicSharedMemorySize, SMEM_DYN);

    cvt_a_kernel<<<(B_ROWS * D_K / 2 + 255) / 256, 256>>>(inputs);
    gemm_hmma_kernel<<<N_FEAT / N_TILE, THREADS, SMEM_DYN>>>(feats, out);
}

// round 9
// speedup vs baseline: 1.3332x; 1.0410x over previous
#include <cuda_runtime.h>
#include <cuda_fp16.h>
#include <cstdint>

#define THREADS     256
#define B_ROWS      256
#define D_K         2048
#define N_FEAT      65536
#define N_TILE      64
#define KC          64
#define NSTAGE      (D_K / KC)            // 32
#define A_ST        (B_ROWS * KC * 2)     // 32768 fp16 A per stage
#define B_ST        (N_TILE * KC * 2)     // 8192  fp16 B per stage
#define SMEM_DYN    (128 + 3 * A_ST + 2 * B_ST)   // 114816

// 1MB fp16 copy of `inputs` (pre-converted once per launch, L2-resident)
__device__ __half g_a16[B_ROWS * D_K];

static __device__ __forceinline__ uint32_t smem_u32(const void* p) {
    uint32_t a;
    asm("{ .reg .u64 t; cvta.to.shared.u64 t, %1; cvt.u32.u64 %0, t; }"
        : "=r"(a) : "l"(p));
    return a;
}

#define CP_ASYNC16(dst, src) \
    asm volatile("cp.async.cg.shared.global [%0], [%1], 16;" \
                 :: "r"(dst), "l"(src) : "memory")
#define CP_COMMIT() asm volatile("cp.async.commit_group;" ::: "memory")
#define CP_WAIT1()  asm volatile("cp.async.wait_group 1;"  ::: "memory")

#define LDSM_X4(r, addr) \
    asm volatile("ldmatrix.sync.aligned.m8n8.x4.shared.b16 {%0,%1,%2,%3}, [%4];" \
        : "=r"((r)[0]), "=r"((r)[1]), "=r"((r)[2]), "=r"((r)[3]) : "r"(addr))

#define MMA16816(c, a, b0, b1) \
    asm volatile("mma.sync.aligned.m16n8k16.row.col.f32.f16.f16.f32 " \
        "{%0,%1,%2,%3}, {%4,%5,%6,%7}, {%8,%9}, {%0,%1,%2,%3};" \
        : "+f"((c)[0]), "+f"((c)[1]), "+f"((c)[2]), "+f"((c)[3]) \
        : "r"((a)[0]), "r"((a)[1]), "r"((a)[2]), "r"((a)[3]), "r"(b0), "r"(b1))

#define STS64(addr, v0, v1) \
    asm volatile("st.shared.v2.b32 [%0], {%1,%2};" \
                 :: "r"(addr), "r"(v0), "r"(v1) : "memory")

// ---------------- pre-kernel: inputs fp32 -> fp16 scratch ----------------
__global__ void cvt_a_kernel(const float* __restrict__ inputs) {
    int i = blockIdx.x * blockDim.x + threadIdx.x;
    if (i < (B_ROWS * D_K) / 2) {
        float2 v = reinterpret_cast<const float2*>(inputs)[i];
        reinterpret_cast<__half2*>(g_a16)[i] = __floats2half2_rn(v.x, v.y);
    }
}

// ---------------- main GEMM kernel ----------------
__global__ __launch_bounds__(THREADS, 2)
void gemm_hmma_kernel(const float* __restrict__ feats, float* __restrict__ out) {
    extern __shared__ char dsm[];
    const uint32_t raw = smem_u32(dsm);
    const uint32_t SB  = (raw + 127u) & ~127u;
    const uint32_t BB0 = SB + 3 * A_ST;

    const int tid = threadIdx.x;
    const int wid = tid >> 5;
    const int lid = tid & 31;
    const int wm  = wid & 3;    // 4 M-warps x 64 rows
    const int wn  = wid >> 2;   // 2 N-warps x 32 cols
    const int n0  = blockIdx.x * N_TILE;

    // ---- A cp.async staging: 256 rows x 128B/stage; 8x16B per thread ----
    const char* aSrc = (const char*)(g_a16 + (size_t)(tid >> 3) * D_K + (tid & 7) * 8);
    const uint32_t aOff = ((uint32_t)(tid >> 3) << 7) |
                          ((uint32_t)((tid & 7) ^ ((tid >> 3) & 7)) << 4);

    // ---- B LDG staging: 64 rows x 64 fp32/stage; 4x float4 per thread ----
    const int brow = tid >> 2;
    const int bj   = tid & 3;
    const float* bSrc = feats + (size_t)(n0 + brow) * D_K + bj * 4;

    // ---- ldmatrix fragment addressing (swizzle-correct per k-step) ----
    const uint32_t a_lane = (uint32_t)(wm * 64 + (lid & 15)) << 7;
    const uint32_t a_sw   = (uint32_t)(lid & 7);
    const uint32_t a_kc   = (uint32_t)(lid >> 4);
    const uint32_t b_row  = (uint32_t)(wn * 32 + ((lid >> 4) << 3) + (lid & 7));
    const uint32_t b_sw   = b_row & 7;
    const uint32_t b_kc   = (uint32_t)((lid >> 3) & 1);

    float acc[4][4][4];
    #pragma unroll
    for (int mf = 0; mf < 4; ++mf)
        #pragma unroll
        for (int nf = 0; nf < 4; ++nf)
            #pragma unroll
            for (int k = 0; k < 4; ++k)
                acc[mf][nf][k] = 0.0f;

    float fst[16];   // staged raw fp32 B for current stage

    // ---- prologue: B(0) LDG; A(0), A(1) cp.async (distance-2 pipeline) ----
    #pragma unroll
    for (int i = 0; i < 4; ++i) {
        const float4 v = *reinterpret_cast<const float4*>(bSrc + i * 16);
        fst[i*4+0] = v.x; fst[i*4+1] = v.y; fst[i*4+2] = v.z; fst[i*4+3] = v.w;
    }
    #pragma unroll
    for (int i = 0; i < 8; ++i)
        CP_ASYNC16(SB + aOff + i * 4096, aSrc + (size_t)i * 32 * D_K * 2);
    CP_COMMIT();
    #pragma unroll
    for (int i = 0; i < 8; ++i)
        CP_ASYNC16(SB + A_ST + aOff + i * 4096,
                   aSrc + (size_t)KC * 2 + (size_t)i * 32 * D_K * 2);
    CP_COMMIT();

    for (int s = 0; s < NSTAGE; ++s) {
        const uint32_t Ab = SB + (uint32_t)(s % 3) * A_ST;
        const uint32_t Bb = BB0 + (uint32_t)(s & 1) * B_ST;

        // STS B(s): convert staged fp32 -> fp16 (swizzle recomputed, ALU-cheap)
        #pragma unroll
        for (int i = 0; i < 4; ++i) {
            __half2 h0 = __floats2half2_rn(fst[i*4+0], fst[i*4+1]);
            __half2 h1 = __floats2half2_rn(fst[i*4+2], fst[i*4+3]);
            uint32_t ob = ((uint32_t)brow << 7) | ((uint32_t)(bj + 4 * i) << 3);
            ob ^= ((ob >> 3) & 0x70);
            STS64(Bb + ob,
                  *reinterpret_cast<uint32_t*>(&h0),
                  *reinterpret_cast<uint32_t*>(&h1));
        }
        CP_WAIT1();          // A(s) landed (A(s+1) may still be in flight)
        __syncthreads();     // single barrier per stage

        // issue A(s+2) + B(s+1) LDG (covered by compute below)
        if (s + 2 < NSTAGE) {
            const uint32_t An = SB + (uint32_t)((s + 2) % 3) * A_ST;
            const char* as = aSrc + (size_t)(s + 2) * (KC * 2);
            #pragma unroll
            for (int i = 0; i < 8; ++i)
                CP_ASYNC16(An + aOff + i * 4096, as + (size_t)i * 32 * D_K * 2);
        }
        CP_COMMIT();
        if (s + 1 < NSTAGE) {
            const int kc1 = (s + 1) * KC;   // FLOAT elements
            #pragma unroll
            for (int i = 0; i < 4; ++i) {
                const float4 v = *reinterpret_cast<const float4*>(bSrc + kc1 + i * 16);
                fst[i*4+0] = v.x; fst[i*4+1] = v.y; fst[i*4+2] = v.z; fst[i*4+3] = v.w;
            }
        }

        // ---- compute stage s: 4 k-steps, software-pipelined fragments ----
        // B frags double-buffered across ksteps; A frags double-buffered across mf.
        uint32_t bq0[8], bq1[8];   // [0..3]=cols 0-15, [4..7]=cols 16-31
        {
            const uint32_t ch0 = ((b_kc) ^ b_sw) << 4;     // ks=0
            LDSM_X4(bq0,     Bb + (b_row << 7) + ch0);
            LDSM_X4(bq0 + 4, Bb + ((b_row + 16u) << 7) + ch0);
        }
        #pragma unroll
        for (int ks = 0; ks < 4; ++ks) {
            uint32_t* bc = (ks & 1) ? bq1 : bq0;
            uint32_t* bn = (ks & 1) ? bq0 : bq1;
            if (ks < 3) {   // prefetch B frags for ks+1 before MMAs
                const uint32_t chn = ((b_kc + 2u * (ks + 1)) ^ b_sw) << 4;
                LDSM_X4(bn,     Bb + (b_row << 7) + chn);
                LDSM_X4(bn + 4, Bb + ((b_row + 16u) << 7) + chn);
            }

            const uint32_t a_ch = ((a_kc + 2u * ks) ^ a_sw) << 4;
            uint32_t aA[4], aB[4];
            LDSM_X4(aA, Ab + a_lane + a_ch);                      // mf=0
            // mf=0: prefetch mf=1, compute with aA
            LDSM_X4(aB, Ab + a_lane + 2048u + a_ch);
            MMA16816(acc[0][0], aA, bc[0], bc[1]);
            MMA16816(acc[0][1], aA, bc[2], bc[3]);
            MMA16816(acc[0][2], aA, bc[4], bc[5]);
            MMA16816(acc[0][3], aA, bc[6], bc[7]);
            // mf=1: prefetch mf=2, compute with aB
            LDSM_X4(aA, Ab + a_lane + 4096u + a_ch);
            MMA16816(acc[1][0], aB, bc[0], bc[1]);
            MMA16816(acc[1][1], aB, bc[2], bc[3]);
            MMA16816(acc[1][2], aB, bc[4], bc[5]);
            MMA16816(acc[1][3], aB, bc[6], bc[7]);
            // mf=2: prefetch mf=3, compute with aA
            LDSM_X4(aB, Ab + a_lane + 6144u + a_ch);
            MMA16816(acc[2][0], aA, bc[0], bc[1]);
            MMA16816(acc[2][1], aA, bc[2], bc[3]);
            MMA16816(acc[2][2], aA, bc[4], bc[5]);
            MMA16816(acc[2][3], aA, bc[6], bc[7]);
            // mf=3: compute with aB
            MMA16816(acc[3][0], aB, bc[0], bc[1]);
            MMA16816(acc[3][1], aB, bc[2], bc[3]);
            MMA16816(acc[3][2], aB, bc[4], bc[5]);
            MMA16816(acc[3][3], aB, bc[6], bc[7]);
        }
        // no trailing barrier: next stage's single sync orders reuse hazards
    }

    // ---- epilogue: direct STG.64, 32B-sector aligned ----
    const int mrow = wm * 64 + (lid >> 2);
    const int ncol = n0 + wn * 32 + 2 * (lid & 3);
    #pragma unroll
    for (int mf = 0; mf < 4; ++mf) {
        float* r0 = out + (size_t)(mrow + mf * 16) * N_FEAT;
        float* r1 = r0 + (size_t)8 * N_FEAT;
        #pragma unroll
        for (int nf = 0; nf < 4; ++nf) {
            const int c = ncol + nf * 8;
            *reinterpret_cast<float2*>(r0 + c) =
                make_float2(acc[mf][nf][0], acc[mf][nf][1]);
            *reinterpret_cast<float2*>(r1 + c) =
                make_float2(acc[mf][nf][2], acc[mf][nf][3]);
        }
    }
}

// ---------------- launch ----------------
extern "C" void kernel_launch(void* const* d_in, const int* in_sizes, int n_in,
                              void* d_out, int out_size) {
    const float* inputs = (const float*)d_in[0];   // [256, 2048] fp32
    const float* feats  = (const float*)d_in[3];   // [65536, 2048] fp32
    float* out = (float*)d_out;                    // [256, 65536] fp32

    cudaFuncSetAttribute(gemm_hmma_kernel,
                         cudaFuncAttributeMaxDynamicSharedMemorySize, SMEM_DYN);

    cvt_a_kernel<<<(B_ROWS * D_K / 2 + 255) / 256, 256>>>(inputs);
    gemm_hmma_kernel<<<N_FEAT / N_TILE, THREADS, SMEM_DYN>>>(feats, out);
}